// round 6
// baseline (speedup 1.0000x reference)
#include <cuda_runtime.h>
#include <cuda_bf16.h>
#include <cuda_fp16.h>
#include <cstdint>
#include <math.h>

#define SSQ  1024
#define DD   1024
#define HHN  16
#define DHD  64
#define BHN  64
#define MTOT 4096
#define ATT_SCALE 0.03125f

// ---------------- scratch ----------------
__device__ __half g_t16[(size_t)BHN * SSQ * SSQ];   // 128 MB, fp16 t matrix

// ---------------- bf16 pool ----------------
#define NX   ((size_t)MTOT * DD)
#define NW   ((size_t)DD * DD)
#define NH   ((size_t)BHN * SSQ * DHD)
#define O_XH  ((size_t)0)
#define O_XL  (O_XH + NX)
#define O_WQH (O_XL + NX)
#define O_WQL (O_WQH + NW)
#define O_WKH (O_WQL + NW)
#define O_WKL (O_WKH + NW)
#define O_WVH (O_WKL + NW)
#define O_WVL (O_WVH + NW)
#define O_WCH (O_WVL + NW)
#define O_WCL (O_WCH + NW)
#define O_QUH (O_WCL + NW)
#define O_QUL (O_QUH + NH)
#define O_QVH (O_QUL + NH)
#define O_QVL (O_QVH + NH)
#define O_KHH (O_QVL + NH)
#define O_KHL (O_KHH + NH)
#define O_RHH (O_KHL + NH)
#define O_RHL (O_RHH + NH)
#define O_VWH (O_RHL + NH)
#define O_VWL (O_VWH + NH)
#define O_OBH (O_VWL + NH)
#define O_OBL (O_OBH + NX)
#define BF_TOTAL (O_OBL + NX)
__device__ __align__(16) __nv_bfloat16 g_bf[BF_TOTAL];

// ================= helpers =================
__device__ __forceinline__ uint32_t smem_u32(const void* p) {
    uint32_t a;
    asm("{ .reg .u64 t; cvta.to.shared.u64 t, %1; cvt.u32.u64 %0, t; }" : "=r"(a) : "l"(p));
    return a;
}
__device__ __forceinline__ void split2(float v, __nv_bfloat16& h, __nv_bfloat16& l) {
    h = __float2bfloat16(v);
    l = __float2bfloat16(v - __bfloat162float(h));
}
__device__ __forceinline__ uint32_t pack_hi(float a, float b) {
    __nv_bfloat162 p(__float2bfloat16(a), __float2bfloat16(b));
    return *(uint32_t*)&p;
}
__device__ __forceinline__ uint32_t pack_lo(float a, float b) {
    __nv_bfloat16 ha = __float2bfloat16(a), hb = __float2bfloat16(b);
    __nv_bfloat162 p(__float2bfloat16(a - __bfloat162float(ha)),
                     __float2bfloat16(b - __bfloat162float(hb)));
    return *(uint32_t*)&p;
}
__device__ __forceinline__ void cp16(uint32_t dst, const void* src) {
    asm volatile("cp.async.cg.shared.global [%0], [%1], 16;" :: "r"(dst), "l"(src));
}
__device__ __forceinline__ void cp_commit() { asm volatile("cp.async.commit_group;"); }
__device__ __forceinline__ void ldsm4(uint32_t& r0, uint32_t& r1, uint32_t& r2, uint32_t& r3,
                                      uint32_t addr) {
    asm volatile("ldmatrix.sync.aligned.m8n8.x4.shared.b16 {%0,%1,%2,%3}, [%4];"
                 : "=r"(r0), "=r"(r1), "=r"(r2), "=r"(r3) : "r"(addr));
}
__device__ __forceinline__ void ldsm4t(uint32_t& r0, uint32_t& r1, uint32_t& r2, uint32_t& r3,
                                       uint32_t addr) {
    asm volatile("ldmatrix.sync.aligned.m8n8.x4.trans.shared.b16 {%0,%1,%2,%3}, [%4];"
                 : "=r"(r0), "=r"(r1), "=r"(r2), "=r"(r3) : "r"(addr));
}
__device__ __forceinline__ void mma_bf16(float* d, const uint32_t* a, const uint32_t* b) {
    asm volatile(
        "mma.sync.aligned.m16n8k16.row.col.f32.bf16.bf16.f32 "
        "{%0,%1,%2,%3}, {%4,%5,%6,%7}, {%8,%9}, {%0,%1,%2,%3};"
        : "+f"(d[0]), "+f"(d[1]), "+f"(d[2]), "+f"(d[3])
        : "r"(a[0]), "r"(a[1]), "r"(a[2]), "r"(a[3]), "r"(b[0]), "r"(b[1]));
}
__device__ __forceinline__ uint32_t swadr(uint32_t tb, int r, int c) {
    return tb + r * 64 + (((c ^ ((r >> 1) & 3))) << 4);
}

#define STAGE_SZ 32768
#define SMEM_BYTES (2 * STAGE_SZ)

__device__ __forceinline__ void stage_load(
    uint32_t sb, const __nv_bfloat16* Ah, const __nv_bfloat16* Al,
    const __nv_bfloat16* Bh, const __nv_bfloat16* Bl,
    int arow0, int brow0, int ldA, int ldB, int k0, int tid)
{
#pragma unroll
    for (int half = 0; half < 2; half++) {
        const int q = half * 256 + tid;
        const int r = q >> 2, c = q & 3;
        const int kel = k0 + c * 8;
        cp16(swadr(sb,          r, c), Ah + (size_t)(arow0 + r) * ldA + kel);
        cp16(swadr(sb +  8192,  r, c), Al + (size_t)(arow0 + r) * ldA + kel);
        cp16(swadr(sb + 16384,  r, c), Bh + (size_t)(brow0 + r) * ldB + kel);
        cp16(swadr(sb + 24576,  r, c), Bl + (size_t)(brow0 + r) * ldB + kel);
    }
}

__device__ __forceinline__ void compute_chunk(uint32_t sb, int wm, int wn, int lane,
                                              float acc[4][4][4])
{
    const uint32_t Ahb = sb, Alb = sb + 8192, Bhb = sb + 16384, Blb = sb + 24576;
#pragma unroll
    for (int kk = 0; kk < 2; kk++) {
        uint32_t ah[4][4], al[4][4], bh[4][2], bl[4][2];
        const int ar = wm * 64 + (lane & 15);
        const int ac = 2 * kk + (lane >> 4);
#pragma unroll
        for (int i = 0; i < 4; i++) {
            ldsm4(ah[i][0], ah[i][1], ah[i][2], ah[i][3], swadr(Ahb, ar + i * 16, ac));
            ldsm4(al[i][0], al[i][1], al[i][2], al[i][3], swadr(Alb, ar + i * 16, ac));
        }
        const int br = wn * 32 + (lane & 7) + ((lane >> 4) << 3);
        const int bc = 2 * kk + ((lane >> 3) & 1);
#pragma unroll
        for (int p = 0; p < 2; p++) {
            uint32_t t0, t1, t2, t3;
            ldsm4(t0, t1, t2, t3, swadr(Bhb, br + p * 16, bc));
            bh[2*p][0] = t0; bh[2*p][1] = t1; bh[2*p+1][0] = t2; bh[2*p+1][1] = t3;
            ldsm4(t0, t1, t2, t3, swadr(Blb, br + p * 16, bc));
            bl[2*p][0] = t0; bl[2*p][1] = t1; bl[2*p+1][0] = t2; bl[2*p+1][1] = t3;
        }
#pragma unroll
        for (int i = 0; i < 4; i++)
#pragma unroll
            for (int j = 0; j < 4; j++) {
                mma_bf16(acc[i][j], ah[i], bh[j]);
                mma_bf16(acc[i][j], ah[i], bl[j]);
                mma_bf16(acc[i][j], al[i], bh[j]);
            }
    }
}

// ================= conversion kernels =================
__global__ __launch_bounds__(256) void conv_split(
    const float* __restrict__ s, __nv_bfloat16* __restrict__ h,
    __nv_bfloat16* __restrict__ l, int n)
{
    int i = blockIdx.x * 256 + threadIdx.x;
    if (i < n) {
        __nv_bfloat16 hh, ll; split2(s[i], hh, ll);
        h[i] = hh; l[i] = ll;
    }
}

__global__ __launch_bounds__(256) void conv_pos(
    const float* __restrict__ pos, __nv_bfloat16* __restrict__ h,
    __nv_bfloat16* __restrict__ l)
{
    int d = blockIdx.x * 256 + threadIdx.x;
    int bh = d >> 16;
    int s  = (d >> 6) & 1023;
    int dd = d & 63;
    int b = bh >> 4, hh_ = bh & 15;
    float v = pos[(((size_t)b << 10) + s) * 1024 + (hh_ << 6) + dd];
    __nv_bfloat16 hb, lb; split2(v, hb, lb);
    h[d] = hb; l[d] = lb;
}

// ================= projection GEMM (mma.sync) =================
__global__ __launch_bounds__(256, 1) void mm_gemm(
    const __nv_bfloat16* __restrict__ Ah, const __nv_bfloat16* __restrict__ Al,
    const __nv_bfloat16* __restrict__ Bh, const __nv_bfloat16* __restrict__ Bl,
    const float* __restrict__ bias, const float* __restrict__ uvec,
    const float* __restrict__ vvec, int mode, float* __restrict__ out_f,
    __nv_bfloat16* __restrict__ o1h, __nv_bfloat16* __restrict__ o1l,
    __nv_bfloat16* __restrict__ o2h, __nv_bfloat16* __restrict__ o2l)
{
    extern __shared__ __align__(16) char smem[];
    const uint32_t sb0 = smem_u32(smem);
    const int tid = threadIdx.x, lane = tid & 31, w = tid >> 5;
    const int wm = w >> 2, wn = w & 3;
    const int m0 = blockIdx.x * 128, n0 = blockIdx.y * 128;

    float acc[4][4][4];
#pragma unroll
    for (int i = 0; i < 4; i++)
#pragma unroll
        for (int j = 0; j < 4; j++)
#pragma unroll
            for (int q = 0; q < 4; q++) acc[i][j][q] = 0.f;

    const int NC = DD / 32;
    stage_load(sb0, Ah, Al, Bh, Bl, m0, n0, DD, DD, 0, tid);
    cp_commit();
    for (int c = 0; c < NC; c++) {
        if (c + 1 < NC) {
            stage_load(sb0 + ((c + 1) & 1) * STAGE_SZ, Ah, Al, Bh, Bl,
                       m0, n0, DD, DD, (c + 1) * 32, tid);
            cp_commit();
            asm volatile("cp.async.wait_group 1;");
        } else {
            asm volatile("cp.async.wait_group 0;");
        }
        __syncthreads();
        compute_chunk(sb0 + (c & 1) * STAGE_SZ, wm, wn, lane, acc);
        __syncthreads();
    }

    const int g = lane >> 2, t2 = (lane & 3) * 2;
#pragma unroll
    for (int i = 0; i < 4; i++) {
#pragma unroll
        for (int j = 0; j < 4; j++) {
#pragma unroll
            for (int half = 0; half < 2; half++) {
                const int grow = m0 + wm * 64 + i * 16 + g + half * 8;
                const int gcol = n0 + wn * 32 + j * 8 + t2;
                float v0 = acc[i][j][half * 2 + 0] + bias[gcol];
                float v1 = acc[i][j][half * 2 + 1] + bias[gcol + 1];
                if (mode == 0) {
                    *(float2*)&out_f[(size_t)grow * DD + gcol] = make_float2(v0, v1);
                } else {
                    const int b = grow >> 10, s = grow & 1023;
                    const int h = gcol >> 6, dd = gcol & 63;
                    const size_t base = (((size_t)(b * HHN + h) << 10) + s) * DHD + dd;
                    if (mode == 2) {
                        __nv_bfloat16 h0, l0, h1, l1;
                        split2(v0, h0, l0); split2(v1, h1, l1);
                        *(__nv_bfloat162*)&o1h[base] = __nv_bfloat162(h0, h1);
                        *(__nv_bfloat162*)&o1l[base] = __nv_bfloat162(l0, l1);
                    } else {
                        __nv_bfloat16 h0, l0, h1, l1;
                        split2(v0 + uvec[dd], h0, l0); split2(v1 + uvec[dd + 1], h1, l1);
                        *(__nv_bfloat162*)&o1h[base] = __nv_bfloat162(h0, h1);
                        *(__nv_bfloat162*)&o1l[base] = __nv_bfloat162(l0, l1);
                        split2(v0 + vvec[dd], h0, l0); split2(v1 + vvec[dd + 1], h1, l1);
                        *(__nv_bfloat162*)&o2h[base] = __nv_bfloat162(h0, h1);
                        *(__nv_bfloat162*)&o2l[base] = __nv_bfloat162(l0, l1);
                    }
                }
            }
        }
    }
}

// ================= t = (q+v) @ r^T, fp16 out =================
__global__ __launch_bounds__(256, 1) void mm_t(
    const __nv_bfloat16* __restrict__ qvh, const __nv_bfloat16* __restrict__ qvl,
    const __nv_bfloat16* __restrict__ rhh, const __nv_bfloat16* __restrict__ rhl,
    __half* __restrict__ tout)
{
    extern __shared__ __align__(16) char smem[];
    const uint32_t sb0 = smem_u32(smem);
    const int tid = threadIdx.x, lane = tid & 31, w = tid >> 5;
    const int wm = w >> 2, wn = w & 3;
    const int bh = blockIdx.z;
    const int m0 = blockIdx.x * 128;
    const int j0 = blockIdx.y * 128;

    const __nv_bfloat16* Ah = qvh + (size_t)bh * SSQ * DHD;
    const __nv_bfloat16* Al = qvl + (size_t)bh * SSQ * DHD;
    const __nv_bfloat16* Bh = rhh + (size_t)bh * SSQ * DHD;
    const __nv_bfloat16* Bl = rhl + (size_t)bh * SSQ * DHD;

    float acc[4][4][4];
#pragma unroll
    for (int i = 0; i < 4; i++)
#pragma unroll
        for (int j = 0; j < 4; j++)
#pragma unroll
            for (int q = 0; q < 4; q++) acc[i][j][q] = 0.f;

    stage_load(sb0, Ah, Al, Bh, Bl, j0, m0, DHD, DHD, 0, tid);
    cp_commit();
    for (int c = 0; c < 2; c++) {
        if (c == 0) {
            stage_load(sb0 + STAGE_SZ, Ah, Al, Bh, Bl, j0, m0, DHD, DHD, 32, tid);
            cp_commit();
            asm volatile("cp.async.wait_group 1;");
        } else {
            asm volatile("cp.async.wait_group 0;");
        }
        __syncthreads();
        compute_chunk(sb0 + c * STAGE_SZ, wm, wn, lane, acc);
        __syncthreads();
    }

    __half* out = tout + (size_t)bh * SSQ * SSQ;
    const int g = lane >> 2, t2 = (lane & 3) * 2;
#pragma unroll
    for (int i = 0; i < 4; i++)
#pragma unroll
        for (int j = 0; j < 4; j++)
#pragma unroll
            for (int half = 0; half < 2; half++) {
                const int grow = j0 + wm * 64 + i * 16 + g + half * 8;
                const int gcol = m0 + wn * 32 + j * 8 + t2;
                *(__half2*)&out[(size_t)grow * SSQ + gcol] =
                    __floats2half2_rn(acc[i][j][half * 2], acc[i][j][half * 2 + 1]);
            }
}

// ================= fused QK^T + rel-shift softmax + PV =================
// smem: K buffers 2x32K at 0,32768; W buffers 2x32K at 65536,98304
#define FA_K0 0
#define FA_K1 32768
#define FA_W0 65536
#define FA_W1 98304
#define FA_SMEM 131072

// K-layout tile loader: [hi s0 8K][hi s1 8K][lo s0 8K][lo s1 8K]
__device__ __forceinline__ void fa_load_k(uint32_t kb, const __nv_bfloat16* hi,
                                          const __nv_bfloat16* lo, int row0, int tid) {
#pragma unroll
    for (int i = 0; i < 8; i++) {
        const int q = i * 256 + tid;             // 0..2047
        const int hl = q >> 10;
        const int qq = q & 1023;
        const int s = qq >> 9;
        const int q2 = qq & 511;
        const int r = q2 >> 2, c = q2 & 3;
        const __nv_bfloat16* src = (hl ? lo : hi) + (size_t)(row0 + r) * DHD + s * 32 + c * 8;
        cp16(swadr(kb + hl * 16384 + s * 8192, r, c), src);
    }
}
// W-layout tile loader: [hi 16K][lo 16K], 128B rows, chunk swizzle
__device__ __forceinline__ void fa_load_w(uint32_t wb, const __nv_bfloat16* hi,
                                          const __nv_bfloat16* lo, int row0, int tid) {
#pragma unroll
    for (int i = 0; i < 8; i++) {
        const int q = i * 256 + tid;
        const int hl = q >> 10;
        const int qq = q & 1023;
        const int r = qq >> 3, c = qq & 7;
        const __nv_bfloat16* src = (hl ? lo : hi) + (size_t)(row0 + r) * DHD + c * 8;
        cp16(wb + hl * 16384 + r * 128 + ((c ^ (r & 7)) << 4), src);
    }
}

__global__ __launch_bounds__(256, 1) void fused_attn(
    const __nv_bfloat16* __restrict__ quh, const __nv_bfloat16* __restrict__ qul,
    const __nv_bfloat16* __restrict__ khh, const __nv_bfloat16* __restrict__ khl,
    const __nv_bfloat16* __restrict__ vwh, const __nv_bfloat16* __restrict__ vwl,
    const __half* __restrict__ t16,
    __nv_bfloat16* __restrict__ obh, __nv_bfloat16* __restrict__ obl)
{
    extern __shared__ __align__(16) char smem[];
    const uint32_t sb = smem_u32(smem);
    const int tid = threadIdx.x, lane = tid & 31, w = tid >> 5;
    const int bh = blockIdx.y;
    const int jblk = blockIdx.x * 128;
    const int jw = jblk + w * 16;
    const int g = lane >> 2, t2 = (lane & 3) * 2;

    const size_t hoff = (size_t)bh * SSQ * DHD;
    const __nv_bfloat16* kh = khh + hoff;
    const __nv_bfloat16* kl = khl + hoff;
    const __nv_bfloat16* wh = vwh + hoff;
    const __nv_bfloat16* wl = vwl + hoff;

    // ---- stage QU into K0 area, ldmatrix q-frags to registers ----
    fa_load_k(sb + FA_K0, quh + hoff, qul + hoff, jblk, tid);
    cp_commit();
    asm volatile("cp.async.wait_group 0;");
    __syncthreads();
    uint32_t qh[4][4], ql[4][4];
    {
        const int ar = w * 16 + (lane & 15);
#pragma unroll
        for (int kk4 = 0; kk4 < 4; kk4++) {
            const int s = kk4 >> 1;
            const int cc = 2 * (kk4 & 1) + (lane >> 4);
            ldsm4(qh[kk4][0], qh[kk4][1], qh[kk4][2], qh[kk4][3],
                  swadr(sb + FA_K0 + s * 8192, ar, cc));
            ldsm4(ql[kk4][0], ql[kk4][1], ql[kk4][2], ql[kk4][3],
                  swadr(sb + FA_K0 + 16384 + s * 8192, ar, cc));
        }
    }
    __syncthreads();

    // t row pointers for this lane's two rows
    const __half* tr0 = t16 + ((size_t)bh * SSQ + jw + g) * SSQ;
    const __half* tr1 = tr0 + (size_t)8 * SSQ;
    const int j0r = jw + g;

    float acc[8][4];
#pragma unroll
    for (int n = 0; n < 8; n++)
#pragma unroll
        for (int q = 0; q < 4; q++) acc[n][q] = 0.f;
    float zlo = 0.f, zhi = 0.f;

    // prefetch tile 0
    fa_load_k(sb + FA_K0, kh, kl, 0, tid);
    fa_load_w(sb + FA_W0, wh, wl, 0, tid);
    cp_commit();

    for (int mt = 0; mt < 8; mt++) {
        if (mt < 7) {
            const uint32_t kb = ((mt + 1) & 1) ? FA_K1 : FA_K0;
            const uint32_t wb = ((mt + 1) & 1) ? FA_W1 : FA_W0;
            fa_load_k(sb + kb, kh, kl, (mt + 1) * 128, tid);
            fa_load_w(sb + wb, wh, wl, (mt + 1) * 128, tid);
            cp_commit();
            asm volatile("cp.async.wait_group 1;");
        } else {
            asm volatile("cp.async.wait_group 0;");
        }
        __syncthreads();

        const uint32_t Kb = sb + ((mt & 1) ? FA_K1 : FA_K0);
        const uint32_t Wb = sb + ((mt & 1) ? FA_W1 : FA_W0);
        const int m0 = mt * 128;

#pragma unroll
        for (int half = 0; half < 2; half++) {
            // ---- ac tile: c[8][4] over 16 rows x 64 cols ----
            float c[8][4];
#pragma unroll
            for (int n = 0; n < 8; n++)
#pragma unroll
                for (int e = 0; e < 4; e++) c[n][e] = 0.f;

#pragma unroll
            for (int kk4 = 0; kk4 < 4; kk4++) {
                const int s = kk4 >> 1;
                const int bc = 2 * (kk4 & 1) + ((lane >> 3) & 1);
                const uint32_t khb = Kb + s * 8192;
                const uint32_t klb = khb + 16384;
#pragma unroll
                for (int p = 0; p < 4; p++) {
                    const int br = half * 64 + p * 16 + (lane & 7) + ((lane >> 4) << 3);
                    uint32_t h0, h1, h2, h3, l0, l1, l2, l3;
                    ldsm4(h0, h1, h2, h3, swadr(khb, br, bc));
                    ldsm4(l0, l1, l2, l3, swadr(klb, br, bc));
                    uint32_t B0h[2] = {h0, h1}, B1h[2] = {h2, h3};
                    uint32_t B0l[2] = {l0, l1}, B1l[2] = {l2, l3};
                    mma_bf16(c[2*p],   qh[kk4], B0h);
                    mma_bf16(c[2*p],   ql[kk4], B0h);
                    mma_bf16(c[2*p],   qh[kk4], B0l);
                    mma_bf16(c[2*p+1], qh[kk4], B1h);
                    mma_bf16(c[2*p+1], ql[kk4], B1h);
                    mma_bf16(c[2*p+1], qh[kk4], B1l);
                }
            }

            // ---- bd gather + exp (in registers) ----
#pragma unroll
            for (int n = 0; n < 8; n++) {
#pragma unroll
                for (int e = 0; e < 4; e++) {
                    const int m = m0 + half * 64 + n * 8 + t2 + (e & 1);
                    const int j = j0r + ((e >> 1) << 3);
                    const int dlt = m - j;
                    float bd = 0.f;
                    if (dlt != 1) {
                        const int idx = dlt + ((dlt <= 0) ? 1023 : 1022);
                        bd = __half2float((e >> 1) ? tr1[idx] : tr0[idx]);
                    }
                    const float sv = __expf((c[n][e] + bd) * ATT_SCALE);
                    c[n][e] = sv;
                    if (e < 2) zlo += sv; else zhi += sv;
                }
            }

            // ---- PV: acc += P * w ----
#pragma unroll
            for (int ks = 0; ks < 4; ks++) {
                uint32_t aph[4], apl[4];
                aph[0] = pack_hi(c[2*ks][0],   c[2*ks][1]);
                aph[1] = pack_hi(c[2*ks][2],   c[2*ks][3]);
                aph[2] = pack_hi(c[2*ks+1][0], c[2*ks+1][1]);
                aph[3] = pack_hi(c[2*ks+1][2], c[2*ks+1][3]);
                apl[0] = pack_lo(c[2*ks][0],   c[2*ks][1]);
                apl[1] = pack_lo(c[2*ks][2],   c[2*ks][3]);
                apl[2] = pack_lo(c[2*ks+1][0], c[2*ks+1][1]);
                apl[3] = pack_lo(c[2*ks+1][2], c[2*ks+1][3]);
                const int krow = half * 64 + ks * 16 + ((lane >> 3) & 1) * 8 + (lane & 7);
#pragma unroll
                for (int g2 = 0; g2 < 4; g2++) {
                    const int nc = g2 * 2 + (lane >> 4);
                    const uint32_t off = krow * 128 + ((nc ^ (krow & 7)) << 4);
                    uint32_t h0, h1, h2, h3, l0, l1, l2, l3;
                    ldsm4t(h0, h1, h2, h3, Wb + off);
                    ldsm4t(l0, l1, l2, l3, Wb + 16384 + off);
                    uint32_t B0[2] = {h0, h1}, B1[2] = {h2, h3};
                    uint32_t C0[2] = {l0, l1}, C1[2] = {l2, l3};
                    mma_bf16(acc[2*g2],   aph, B0);
                    mma_bf16(acc[2*g2],   apl, B0);
                    mma_bf16(acc[2*g2],   aph, C0);
                    mma_bf16(acc[2*g2+1], aph, B1);
                    mma_bf16(acc[2*g2+1], apl, B1);
                    mma_bf16(acc[2*g2+1], aph, C1);
                }
            }
        }
        __syncthreads();
    }

    // ---- z reduce within quad (lanes differ in t only) ----
    zlo += __shfl_xor_sync(0xffffffffu, zlo, 1);
    zlo += __shfl_xor_sync(0xffffffffu, zlo, 2);
    zhi += __shfl_xor_sync(0xffffffffu, zhi, 1);
    zhi += __shfl_xor_sync(0xffffffffu, zhi, 2);
    const float inv0 = 1.f / zlo, inv1 = 1.f / zhi;

    // ---- epilogue: write bf16 hi/lo merged-head ----
    const int b = bh >> 4, h = bh & 15;
    const size_t rb0 = ((size_t)(b << 10) + jw + g) << 10;
    const size_t rb1 = ((size_t)(b << 10) + jw + g + 8) << 10;
#pragma unroll
    for (int ng = 0; ng < 8; ng++) {
        const int d = h * 64 + ng * 8 + t2;
        __nv_bfloat16 h0, l0, h1, l1;
        split2(acc[ng][0] * inv0, h0, l0); split2(acc[ng][1] * inv0, h1, l1);
        *(__nv_bfloat162*)&obh[rb0 + d] = __nv_bfloat162(h0, h1);
        *(__nv_bfloat162*)&obl[rb0 + d] = __nv_bfloat162(l0, l1);
        split2(acc[ng][2] * inv1, h0, l0); split2(acc[ng][3] * inv1, h1, l1);
        *(__nv_bfloat162*)&obh[rb1 + d] = __nv_bfloat162(h0, h1);
        *(__nv_bfloat162*)&obl[rb1 + d] = __nv_bfloat162(l0, l1);
    }
}

// =====================================================================
extern "C" void kernel_launch(void* const* d_in, const int* in_sizes, int n_in,
                              void* d_out, int out_size)
{
    const float* x   = (const float*)d_in[0];
    const float* u   = (const float*)d_in[1];
    const float* v   = (const float*)d_in[2];
    const float* pos = (const float*)d_in[3];
    const float* Wq  = (const float*)d_in[4];
    const float* bq  = (const float*)d_in[5];
    const float* Wk  = (const float*)d_in[6];
    const float* bk  = (const float*)d_in[7];
    const float* Wv  = (const float*)d_in[8];
    const float* bv  = (const float*)d_in[9];
    const float* Wc  = (const float*)d_in[10];
    const float* bc  = (const float*)d_in[11];
    float* out = (float*)d_out;

    __half* t16;
    __nv_bfloat16* bf;
    cudaGetSymbolAddress((void**)&t16, g_t16);
    cudaGetSymbolAddress((void**)&bf,  g_bf);

    cudaFuncSetAttribute(mm_gemm, cudaFuncAttributeMaxDynamicSharedMemorySize, SMEM_BYTES);
    cudaFuncSetAttribute(mm_t,    cudaFuncAttributeMaxDynamicSharedMemorySize, SMEM_BYTES);
    cudaFuncSetAttribute(fused_attn, cudaFuncAttributeMaxDynamicSharedMemorySize, FA_SMEM);

    conv_split<<<(int)((NX + 255) / 256), 256>>>(x,  bf + O_XH,  bf + O_XL,  (int)NX);
    conv_split<<<(int)((NW + 255) / 256), 256>>>(Wq, bf + O_WQH, bf + O_WQL, (int)NW);
    conv_split<<<(int)((NW + 255) / 256), 256>>>(Wk, bf + O_WKH, bf + O_WKL, (int)NW);
    conv_split<<<(int)((NW + 255) / 256), 256>>>(Wv, bf + O_WVH, bf + O_WVL, (int)NW);
    conv_split<<<(int)((NW + 255) / 256), 256>>>(Wc, bf + O_WCH, bf + O_WCL, (int)NW);
    conv_pos  <<<(int)((NH + 255) / 256), 256>>>(pos, bf + O_RHH, bf + O_RHL);

    dim3 gp(32, 8);
    mm_gemm<<<gp, 256, SMEM_BYTES>>>(bf + O_XH, bf + O_XL, bf + O_WQH, bf + O_WQL,
        bq, u, v, 1, nullptr,
        bf + O_QUH, bf + O_QUL, bf + O_QVH, bf + O_QVL);
    mm_gemm<<<gp, 256, SMEM_BYTES>>>(bf + O_XH, bf + O_XL, bf + O_WKH, bf + O_WKL,
        bk, u, v, 2, nullptr,
        bf + O_KHH, bf + O_KHL, nullptr, nullptr);
    mm_gemm<<<gp, 256, SMEM_BYTES>>>(bf + O_XH, bf + O_XL, bf + O_WVH, bf + O_WVL,
        bv, u, v, 2, nullptr,
        bf + O_VWH, bf + O_VWL, nullptr, nullptr);

    mm_t<<<dim3(8, 8, 64), 256, SMEM_BYTES>>>(
        bf + O_QVH, bf + O_QVL, bf + O_RHH, bf + O_RHL, t16);

    fused_attn<<<dim3(8, 64), 256, FA_SMEM>>>(
        bf + O_QUH, bf + O_QUL, bf + O_KHH, bf + O_KHL,
        bf + O_VWH, bf + O_VWL, t16, bf + O_OBH, bf + O_OBL);

    mm_gemm<<<gp, 256, SMEM_BYTES>>>(bf + O_OBH, bf + O_OBL, bf + O_WCH, bf + O_WCL,
        bc, u, v, 0, out, nullptr, nullptr, nullptr, nullptr);
}

// round 8
// speedup vs baseline: 1.5827x; 1.5827x over previous
#include <cuda_runtime.h>
#include <cuda_fp16.h>
#include <cstdint>
#include <math.h>

#define SSQ  1024
#define DD   1024
#define HHN  16
#define DHD  64
#define BHN  64
#define MTOT 4096
#define ATT_SCALE 0.03125f

// ---------------- scratch ----------------
__device__ __half g_t16[(size_t)BHN * SSQ * SSQ];   // 128 MB fp16 t

// ---------------- fp16 pool ----------------
#define NX   ((size_t)MTOT * DD)
#define NW   ((size_t)DD * DD)
#define NH   ((size_t)BHN * SSQ * DHD)
#define O_XH  ((size_t)0)
#define O_WQH (O_XH + NX)
#define O_WQL (O_WQH + NW)
#define O_WKH (O_WQL + NW)
#define O_WKL (O_WKH + NW)
#define O_WVH (O_WKL + NW)
#define O_WVL (O_WVH + NW)
#define O_WCH (O_WVL + NW)
#define O_WCL (O_WCH + NW)
#define O_QUH (O_WCL + NW)
#define O_QVH (O_QUH + NH)
#define O_KHH (O_QVH + NH)
#define O_RHH (O_KHH + NH)
#define O_VWH (O_RHH + NH)
#define O_OBH (O_VWH + NH)
#define HF_TOTAL (O_OBH + NX)
__device__ __align__(16) __half g_hf[HF_TOTAL];

// ================= helpers =================
__device__ __forceinline__ uint32_t smem_u32(const void* p) {
    uint32_t a;
    asm("{ .reg .u64 t; cvta.to.shared.u64 t, %1; cvt.u32.u64 %0, t; }" : "=r"(a) : "l"(p));
    return a;
}
__device__ __forceinline__ void splith(float v, __half& h, __half& l) {
    h = __float2half_rn(v);
    l = __float2half_rn(v - __half2float(h));
}
__device__ __forceinline__ uint32_t packh2(float a, float b) {
    __half2 p = __floats2half2_rn(a, b);
    return *(uint32_t*)&p;
}
__device__ __forceinline__ void cp16(uint32_t dst, const void* src) {
    asm volatile("cp.async.cg.shared.global [%0], [%1], 16;" :: "r"(dst), "l"(src));
}
__device__ __forceinline__ void cp_commit() { asm volatile("cp.async.commit_group;"); }
__device__ __forceinline__ void ldsm4(uint32_t& r0, uint32_t& r1, uint32_t& r2, uint32_t& r3,
                                      uint32_t addr) {
    asm volatile("ldmatrix.sync.aligned.m8n8.x4.shared.b16 {%0,%1,%2,%3}, [%4];"
                 : "=r"(r0), "=r"(r1), "=r"(r2), "=r"(r3) : "r"(addr));
}
__device__ __forceinline__ void ldsm4t(uint32_t& r0, uint32_t& r1, uint32_t& r2, uint32_t& r3,
                                       uint32_t addr) {
    asm volatile("ldmatrix.sync.aligned.m8n8.x4.trans.shared.b16 {%0,%1,%2,%3}, [%4];"
                 : "=r"(r0), "=r"(r1), "=r"(r2), "=r"(r3) : "r"(addr));
}
__device__ __forceinline__ void mma_f16(float* d, const uint32_t* a, const uint32_t* b) {
    asm volatile(
        "mma.sync.aligned.m16n8k16.row.col.f32.f16.f16.f32 "
        "{%0,%1,%2,%3}, {%4,%5,%6,%7}, {%8,%9}, {%0,%1,%2,%3};"
        : "+f"(d[0]), "+f"(d[1]), "+f"(d[2]), "+f"(d[3])
        : "r"(a[0]), "r"(a[1]), "r"(a[2]), "r"(a[3]), "r"(b[0]), "r"(b[1]));
}
__device__ __forceinline__ uint32_t swadr(uint32_t tb, int r, int c) {
    return tb + r * 64 + (((c ^ ((r >> 1) & 3))) << 4);
}

// ================= conv_all: x, 4 weights(hi/lo), pos(head-major) ======
__global__ __launch_bounds__(256) void conv_all(
    const float* __restrict__ x, const float* __restrict__ Wq,
    const float* __restrict__ Wk, const float* __restrict__ Wv,
    const float* __restrict__ Wc, const float* __restrict__ pos,
    __half* __restrict__ hf)
{
    const size_t i = (size_t)blockIdx.x * 256 + threadIdx.x;
    if (i < NX) {
        hf[O_XH + i] = __float2half_rn(x[i]);
        return;
    }
    size_t j = i - NX;
    if (j < 4 * NW) {
        const int wi = (int)(j >> 20);
        const size_t off = j & (NW - 1);
        const float* W = (wi == 0) ? Wq : (wi == 1) ? Wk : (wi == 2) ? Wv : Wc;
        __half h, l; splith(W[off], h, l);
        const size_t base = O_WQH + (size_t)wi * 2 * NW;
        hf[base + off] = h;
        hf[base + NW + off] = l;
        return;
    }
    j -= 4 * NW;   // pos head-major
    const int bh = (int)(j >> 16);
    const int s  = (int)((j >> 6) & 1023);
    const int dd = (int)(j & 63);
    const int b = bh >> 4, hh_ = bh & 15;
    hf[O_RHH + j] = __float2half_rn(pos[(((size_t)b << 10) + s) * 1024 + (hh_ << 6) + dd]);
}

// ================= 2-pass projection GEMM (A hi, B hi+lo) =============
#define STAGE2_SZ 24576
#define GEMM_SMEM (2 * STAGE2_SZ)

__device__ __forceinline__ void stage_load2(
    uint32_t sb, const __half* Ah, const __half* Bh, const __half* Bl,
    int arow0, int brow0, int k0, int tid)
{
#pragma unroll
    for (int it = 0; it < 6; it++) {
        const int q = it * 256 + tid;          // 0..1535
        const int region = q >> 9;             // 0:A 1:Bh 2:Bl
        const int q2 = q & 511;
        const int r = q2 >> 2, c = q2 & 3;
        const int kel = k0 + c * 8;
        const __half* src = (region == 0) ? (Ah + (size_t)(arow0 + r) * DD + kel)
                         : (region == 1) ? (Bh + (size_t)(brow0 + r) * DD + kel)
                                         : (Bl + (size_t)(brow0 + r) * DD + kel);
        cp16(swadr(sb + region * 8192, r, c), src);
    }
}

__device__ __forceinline__ void compute_chunk2(uint32_t sb, int wm, int wn, int lane,
                                               float acc[4][4][4])
{
    const uint32_t Ab = sb, Bhb = sb + 8192, Blb = sb + 16384;
#pragma unroll
    for (int kk = 0; kk < 2; kk++) {
        uint32_t a[4][4], bh[4][2], bl[4][2];
        const int ar = wm * 64 + (lane & 15);
        const int ac = 2 * kk + (lane >> 4);
#pragma unroll
        for (int i = 0; i < 4; i++)
            ldsm4(a[i][0], a[i][1], a[i][2], a[i][3], swadr(Ab, ar + i * 16, ac));
        const int br = wn * 32 + (lane & 7) + ((lane >> 4) << 3);
        const int bc = 2 * kk + ((lane >> 3) & 1);
#pragma unroll
        for (int p = 0; p < 2; p++) {
            uint32_t t0, t1, t2, t3;
            ldsm4(t0, t1, t2, t3, swadr(Bhb, br + p * 16, bc));
            bh[2*p][0] = t0; bh[2*p][1] = t1; bh[2*p+1][0] = t2; bh[2*p+1][1] = t3;
            ldsm4(t0, t1, t2, t3, swadr(Blb, br + p * 16, bc));
            bl[2*p][0] = t0; bl[2*p][1] = t1; bl[2*p+1][0] = t2; bl[2*p+1][1] = t3;
        }
#pragma unroll
        for (int i = 0; i < 4; i++)
#pragma unroll
            for (int j = 0; j < 4; j++) {
                mma_f16(acc[i][j], a[i], bh[j]);
                mma_f16(acc[i][j], a[i], bl[j]);
            }
    }
}

// mode 0: fp32 [m][n]; 1: (c+u)->o1h,(c+v)->o2h; 2: c->o1h   (head-major fp16)
__global__ __launch_bounds__(256, 1) void mm_gemm(
    const __half* __restrict__ Ah, const __half* __restrict__ Bh,
    const __half* __restrict__ Bl, const float* __restrict__ bias,
    const float* __restrict__ uvec, const float* __restrict__ vvec,
    int mode, float* __restrict__ out_f,
    __half* __restrict__ o1h, __half* __restrict__ o2h)
{
    extern __shared__ __align__(16) char smem[];
    const uint32_t sb0 = smem_u32(smem);
    const int tid = threadIdx.x, lane = tid & 31, w = tid >> 5;
    const int wm = w >> 2, wn = w & 3;
    const int m0 = blockIdx.x * 128, n0 = blockIdx.y * 128;

    float acc[4][4][4];
#pragma unroll
    for (int i = 0; i < 4; i++)
#pragma unroll
        for (int j = 0; j < 4; j++)
#pragma unroll
            for (int q = 0; q < 4; q++) acc[i][j][q] = 0.f;

    stage_load2(sb0, Ah, Bh, Bl, m0, n0, 0, tid);
    cp_commit();
    for (int c = 0; c < 32; c++) {
        if (c + 1 < 32) {
            stage_load2(sb0 + ((c + 1) & 1) * STAGE2_SZ, Ah, Bh, Bl, m0, n0,
                        (c + 1) * 32, tid);
            cp_commit();
            asm volatile("cp.async.wait_group 1;");
        } else {
            asm volatile("cp.async.wait_group 0;");
        }
        __syncthreads();
        compute_chunk2(sb0 + (c & 1) * STAGE2_SZ, wm, wn, lane, acc);
        __syncthreads();
    }

    const int g = lane >> 2, t2 = (lane & 3) * 2;
#pragma unroll
    for (int i = 0; i < 4; i++)
#pragma unroll
        for (int j = 0; j < 4; j++)
#pragma unroll
            for (int half = 0; half < 2; half++) {
                const int grow = m0 + wm * 64 + i * 16 + g + half * 8;
                const int gcol = n0 + wn * 32 + j * 8 + t2;
                float v0 = acc[i][j][half * 2 + 0] + bias[gcol];
                float v1 = acc[i][j][half * 2 + 1] + bias[gcol + 1];
                if (mode == 0) {
                    *(float2*)&out_f[(size_t)grow * DD + gcol] = make_float2(v0, v1);
                } else {
                    const int b = grow >> 10, s = grow & 1023;
                    const int h = gcol >> 6, dd = gcol & 63;
                    const size_t base = (((size_t)(b * HHN + h) << 10) + s) * DHD + dd;
                    if (mode == 2) {
                        *(__half2*)&o1h[base] = __floats2half2_rn(v0, v1);
                    } else {
                        *(__half2*)&o1h[base] = __floats2half2_rn(v0 + uvec[dd], v1 + uvec[dd + 1]);
                        *(__half2*)&o2h[base] = __floats2half2_rn(v0 + vvec[dd], v1 + vvec[dd + 1]);
                    }
                }
            }
}

// ================= t = (q+v)@r^T single-pass fp16 ======================
#define TSTAGE_SZ 16384
#define T_SMEM (2 * TSTAGE_SZ)

__global__ __launch_bounds__(256, 1) void mm_t(
    const __half* __restrict__ qvh, const __half* __restrict__ rhh,
    __half* __restrict__ tout)
{
    extern __shared__ __align__(16) char smem[];
    const uint32_t sb0 = smem_u32(smem);
    const int tid = threadIdx.x, lane = tid & 31, w = tid >> 5;
    const int wm = w >> 2, wn = w & 3;
    const int bh = blockIdx.z;
    const int m0 = blockIdx.x * 128;
    const int j0 = blockIdx.y * 128;

    const __half* A = qvh + (size_t)bh * SSQ * DHD;
    const __half* B = rhh + (size_t)bh * SSQ * DHD;

    float acc[4][4][4];
#pragma unroll
    for (int i = 0; i < 4; i++)
#pragma unroll
        for (int j = 0; j < 4; j++)
#pragma unroll
            for (int q = 0; q < 4; q++) acc[i][j][q] = 0.f;

#pragma unroll
    for (int c = 0; c < 2; c++) {
        const uint32_t sb = sb0 + c * TSTAGE_SZ;
#pragma unroll
        for (int it = 0; it < 4; it++) {
            const int q = it * 256 + tid;      // 0..1023
            const int region = q >> 9;
            const int q2 = q & 511;
            const int r = q2 >> 2, cc = q2 & 3;
            const int kel = c * 32 + cc * 8;
            const __half* src = region ? (B + (size_t)(m0 + r) * DHD + kel)
                                       : (A + (size_t)(j0 + r) * DHD + kel);
            cp16(swadr(sb + region * 8192, r, cc), src);
        }
        cp_commit();
    }
    asm volatile("cp.async.wait_group 0;");
    __syncthreads();

#pragma unroll
    for (int c = 0; c < 2; c++) {
        const uint32_t Ab = sb0 + c * TSTAGE_SZ, Bb = Ab + 8192;
#pragma unroll
        for (int kk = 0; kk < 2; kk++) {
            uint32_t a[4][4], bfr[4][2];
            const int ar = wm * 64 + (lane & 15);
            const int ac = 2 * kk + (lane >> 4);
#pragma unroll
            for (int i = 0; i < 4; i++)
                ldsm4(a[i][0], a[i][1], a[i][2], a[i][3], swadr(Ab, ar + i * 16, ac));
            const int br = wn * 32 + (lane & 7) + ((lane >> 4) << 3);
            const int bc = 2 * kk + ((lane >> 3) & 1);
#pragma unroll
            for (int p = 0; p < 2; p++) {
                uint32_t t0, t1, t2, t3;
                ldsm4(t0, t1, t2, t3, swadr(Bb, br + p * 16, bc));
                bfr[2*p][0] = t0; bfr[2*p][1] = t1; bfr[2*p+1][0] = t2; bfr[2*p+1][1] = t3;
            }
#pragma unroll
            for (int i = 0; i < 4; i++)
#pragma unroll
                for (int j = 0; j < 4; j++)
                    mma_f16(acc[i][j], a[i], bfr[j]);
        }
    }

    __half* out = tout + (size_t)bh * SSQ * SSQ;
    const int g = lane >> 2, t2 = (lane & 3) * 2;
#pragma unroll
    for (int i = 0; i < 4; i++)
#pragma unroll
        for (int j = 0; j < 4; j++)
#pragma unroll
            for (int half = 0; half < 2; half++) {
                const int grow = j0 + wm * 64 + i * 16 + g + half * 8;
                const int gcol = m0 + wn * 32 + j * 8 + t2;
                *(__half2*)&out[(size_t)grow * SSQ + gcol] =
                    __floats2half2_rn(acc[i][j][half * 2], acc[i][j][half * 2 + 1]);
            }
}

// ================= fused QK^T + rel-shift softmax + PV (single-pass) ===
#define FA_K0 0
#define FA_K1 16384
#define FA_W0 32768
#define FA_W1 49152
#define FA_SMEM 65536

__device__ __forceinline__ void fa_load_k(uint32_t kb, const __half* src0,
                                          int row0, int tid) {
#pragma unroll
    for (int i = 0; i < 4; i++) {
        const int q = i * 256 + tid;           // 0..1023
        const int s = q >> 9;
        const int q2 = q & 511;
        const int r = q2 >> 2, c = q2 & 3;
        cp16(swadr(kb + s * 8192, r, c), src0 + (size_t)(row0 + r) * DHD + s * 32 + c * 8);
    }
}
__device__ __forceinline__ void fa_load_w(uint32_t wb, const __half* src0,
                                          int row0, int tid) {
#pragma unroll
    for (int i = 0; i < 4; i++) {
        const int q = i * 256 + tid;
        const int r = q >> 3, c = q & 7;
        cp16(wb + r * 128 + ((c ^ (r & 7)) << 4), src0 + (size_t)(row0 + r) * DHD + c * 8);
    }
}

__global__ __launch_bounds__(256, 2) void fused_attn(
    const __half* __restrict__ quh, const __half* __restrict__ khh,
    const __half* __restrict__ vwh, const __half* __restrict__ t16,
    __half* __restrict__ obh)
{
    extern __shared__ __align__(16) char smem[];
    const uint32_t sb = smem_u32(smem);
    const int tid = threadIdx.x, lane = tid & 31, w = tid >> 5;
    const int bh = blockIdx.y;
    const int jblk = blockIdx.x * 128;
    const int jw = jblk + w * 16;
    const int g = lane >> 2, t2 = (lane & 3) * 2;

    const size_t hoff = (size_t)bh * SSQ * DHD;
    const __half* kh = khh + hoff;
    const __half* wh = vwh + hoff;

    // stage QU into K0, pull q-frags to registers
    fa_load_k(sb + FA_K0, quh + hoff, jblk, tid);
    cp_commit();
    asm volatile("cp.async.wait_group 0;");
    __syncthreads();
    uint32_t qh[4][4];
    {
        const int ar = w * 16 + (lane & 15);
#pragma unroll
        for (int kk4 = 0; kk4 < 4; kk4++) {
            const int s = kk4 >> 1;
            const int cc = 2 * (kk4 & 1) + (lane >> 4);
            ldsm4(qh[kk4][0], qh[kk4][1], qh[kk4][2], qh[kk4][3],
                  swadr(sb + FA_K0 + s * 8192, ar, cc));
        }
    }
    __syncthreads();

    const __half* tr0 = t16 + ((size_t)bh * SSQ + jw + g) * SSQ;
    const __half* tr1 = tr0 + (size_t)8 * SSQ;
    const int j0r = jw + g;

    float acc[8][4];
#pragma unroll
    for (int n = 0; n < 8; n++)
#pragma unroll
        for (int q = 0; q < 4; q++) acc[n][q] = 0.f;
    float zlo = 0.f, zhi = 0.f;

    fa_load_k(sb + FA_K0, kh, 0, tid);
    fa_load_w(sb + FA_W0, wh, 0, tid);
    cp_commit();

    for (int mt = 0; mt < 8; mt++) {
        if (mt < 7) {
            const uint32_t kb = ((mt + 1) & 1) ? FA_K1 : FA_K0;
            const uint32_t wb = ((mt + 1) & 1) ? FA_W1 : FA_W0;
            fa_load_k(sb + kb, kh, (mt + 1) * 128, tid);
            fa_load_w(sb + wb, wh, (mt + 1) * 128, tid);
            cp_commit();
            asm volatile("cp.async.wait_group 1;");
        } else {
            asm volatile("cp.async.wait_group 0;");
        }
        __syncthreads();

        const uint32_t Kb = sb + ((mt & 1) ? FA_K1 : FA_K0);
        const uint32_t Wb = sb + ((mt & 1) ? FA_W1 : FA_W0);
        const int m0 = mt * 128;

#pragma unroll
        for (int half = 0; half < 2; half++) {
            float c[8][4];
#pragma unroll
            for (int n = 0; n < 8; n++)
#pragma unroll
                for (int e = 0; e < 4; e++) c[n][e] = 0.f;

            // QK^T single-pass
#pragma unroll
            for (int kk4 = 0; kk4 < 4; kk4++) {
                const int s = kk4 >> 1;
                const int bc = 2 * (kk4 & 1) + ((lane >> 3) & 1);
                const uint32_t khb = Kb + s * 8192;
#pragma unroll
                for (int p = 0; p < 4; p++) {
                    const int br = half * 64 + p * 16 + (lane & 7) + ((lane >> 4) << 3);
                    uint32_t h0, h1, h2, h3;
                    ldsm4(h0, h1, h2, h3, swadr(khb, br, bc));
                    uint32_t B0[2] = {h0, h1}, B1[2] = {h2, h3};
                    mma_f16(c[2*p],   qh[kk4], B0);
                    mma_f16(c[2*p+1], qh[kk4], B1);
                }
            }

            // bd gather + exp
#pragma unroll
            for (int n = 0; n < 8; n++) {
#pragma unroll
                for (int e = 0; e < 4; e++) {
                    const int m = m0 + half * 64 + n * 8 + t2 + (e & 1);
                    const int j = j0r + ((e >> 1) << 3);
                    const int dlt = m - j;
                    float bd = 0.f;
                    if (dlt != 1) {
                        const int idx = dlt + ((dlt <= 0) ? 1023 : 1022);
                        bd = __half2float((e >> 1) ? tr1[idx] : tr0[idx]);
                    }
                    const float sv = __expf((c[n][e] + bd) * ATT_SCALE);
                    c[n][e] = sv;
                    if (e < 2) zlo += sv; else zhi += sv;
                }
            }

            // PV single-pass
#pragma unroll
            for (int ks = 0; ks < 4; ks++) {
                uint32_t aph[4];
                aph[0] = packh2(c[2*ks][0],   c[2*ks][1]);
                aph[1] = packh2(c[2*ks][2],   c[2*ks][3]);
                aph[2] = packh2(c[2*ks+1][0], c[2*ks+1][1]);
                aph[3] = packh2(c[2*ks+1][2], c[2*ks+1][3]);
                const int krow = half * 64 + ks * 16 + ((lane >> 3) & 1) * 8 + (lane & 7);
#pragma unroll
                for (int g2 = 0; g2 < 4; g2++) {
                    const int nc = g2 * 2 + (lane >> 4);
                    const uint32_t off = krow * 128 + ((nc ^ (krow & 7)) << 4);
                    uint32_t h0, h1, h2, h3;
                    ldsm4t(h0, h1, h2, h3, Wb + off);
                    uint32_t B0[2] = {h0, h1}, B1[2] = {h2, h3};
                    mma_f16(acc[2*g2],   aph, B0);
                    mma_f16(acc[2*g2+1], aph, B1);
                }
            }
        }
        __syncthreads();
    }

    zlo += __shfl_xor_sync(0xffffffffu, zlo, 1);
    zlo += __shfl_xor_sync(0xffffffffu, zlo, 2);
    zhi += __shfl_xor_sync(0xffffffffu, zhi, 1);
    zhi += __shfl_xor_sync(0xffffffffu, zhi, 2);
    const float inv0 = 1.f / zlo, inv1 = 1.f / zhi;

    const int b = bh >> 4, h = bh & 15;
    const size_t rb0 = ((size_t)(b << 10) + jw + g) << 10;
    const size_t rb1 = ((size_t)(b << 10) + jw + g + 8) << 10;
#pragma unroll
    for (int ng = 0; ng < 8; ng++) {
        const int d = h * 64 + ng * 8 + t2;
        *(__half2*)&obh[rb0 + d] = __floats2half2_rn(acc[ng][0] * inv0, acc[ng][1] * inv0);
        *(__half2*)&obh[rb1 + d] = __floats2half2_rn(acc[ng][2] * inv1, acc[ng][3] * inv1);
    }
}

// =====================================================================
extern "C" void kernel_launch(void* const* d_in, const int* in_sizes, int n_in,
                              void* d_out, int out_size)
{
    const float* x   = (const float*)d_in[0];
    const float* u   = (const float*)d_in[1];
    const float* v   = (const float*)d_in[2];
    const float* pos = (const float*)d_in[3];
    const float* Wq  = (const float*)d_in[4];
    const float* bq  = (const float*)d_in[5];
    const float* Wk  = (const float*)d_in[6];
    const float* bk  = (const float*)d_in[7];
    const float* Wv  = (const float*)d_in[8];
    const float* bv  = (const float*)d_in[9];
    const float* Wc  = (const float*)d_in[10];
    const float* bc  = (const float*)d_in[11];
    float* out = (float*)d_out;

    __half *t16, *hf;
    cudaGetSymbolAddress((void**)&t16, g_t16);
    cudaGetSymbolAddress((void**)&hf,  g_hf);

    cudaFuncSetAttribute(mm_gemm, cudaFuncAttributeMaxDynamicSharedMemorySize, GEMM_SMEM);
    cudaFuncSetAttribute(mm_t,    cudaFuncAttributeMaxDynamicSharedMemorySize, T_SMEM);
    cudaFuncSetAttribute(fused_attn, cudaFuncAttributeMaxDynamicSharedMemorySize, FA_SMEM);

    // 1: conversions (x hi, weights hi/lo, pos head-major hi)
    const size_t total = NX + 4 * NW + NH;
    conv_all<<<(int)((total + 255) / 256), 256>>>(x, Wq, Wk, Wv, Wc, pos, hf);

    dim3 gp(32, 8);
    // 2-4: projections
    mm_gemm<<<gp, 256, GEMM_SMEM>>>(hf + O_XH, hf + O_WQH, hf + O_WQL,
        bq, u, v, 1, nullptr, hf + O_QUH, hf + O_QVH);
    mm_gemm<<<gp, 256, GEMM_SMEM>>>(hf + O_XH, hf + O_WKH, hf + O_WKL,
        bk, u, v, 2, nullptr, hf + O_KHH, nullptr);
    mm_gemm<<<gp, 256, GEMM_SMEM>>>(hf + O_XH, hf + O_WVH, hf + O_WVL,
        bv, u, v, 2, nullptr, hf + O_VWH, nullptr);

    // 5: t matrix
    mm_t<<<dim3(8, 8, 64), 256, T_SMEM>>>(hf + O_QVH, hf + O_RHH, t16);

    // 6: fused attention  (this is the ncu-profiled launch)
    fused_attn<<<dim3(8, 64), 256, FA_SMEM>>>(
        hf + O_QUH, hf + O_KHH, hf + O_VWH, t16, hf + O_OBH);

    // 7: output projection
    mm_gemm<<<gp, 256, GEMM_SMEM>>>(hf + O_OBH, hf + O_WCH, hf + O_WCL,
        bc, u, v, 0, out, nullptr, nullptr);
}

// round 9
// speedup vs baseline: 1.5973x; 1.0092x over previous
#include <cuda_runtime.h>
#include <cuda_fp16.h>
#include <cstdint>
#include <math.h>

#define SSQ  1024
#define DD   1024
#define HHN  16
#define DHD  64
#define BHN  64
#define MTOT 4096
#define ATT_SCALE 0.03125f

// ---------------- scratch ----------------
__device__ __half g_t16[(size_t)BHN * SSQ * SSQ];   // 128 MB fp16 t

// ---------------- fp16 pool ----------------
#define NX   ((size_t)MTOT * DD)
#define NW   ((size_t)DD * DD)
#define NH   ((size_t)BHN * SSQ * DHD)
#define O_XH  ((size_t)0)
#define O_WQH (O_XH + NX)
#define O_WQL (O_WQH + NW)
#define O_WKH (O_WQL + NW)
#define O_WKL (O_WKH + NW)
#define O_WVH (O_WKL + NW)
#define O_WVL (O_WVH + NW)
#define O_WCH (O_WVL + NW)
#define O_WCL (O_WCH + NW)
#define O_QUH (O_WCL + NW)
#define O_QVH (O_QUH + NH)
#define O_KHH (O_QVH + NH)
#define O_RHH (O_KHH + NH)
#define O_VWH (O_RHH + NH)
#define O_OBH (O_VWH + NH)
#define HF_TOTAL (O_OBH + NX)
__device__ __align__(16) __half g_hf[HF_TOTAL];

// ================= helpers =================
__device__ __forceinline__ uint32_t smem_u32(const void* p) {
    uint32_t a;
    asm("{ .reg .u64 t; cvta.to.shared.u64 t, %1; cvt.u32.u64 %0, t; }" : "=r"(a) : "l"(p));
    return a;
}
__device__ __forceinline__ void splith(float v, __half& h, __half& l) {
    h = __float2half_rn(v);
    l = __float2half_rn(v - __half2float(h));
}
__device__ __forceinline__ uint32_t packh2(float a, float b) {
    __half2 p = __floats2half2_rn(a, b);
    return *(uint32_t*)&p;
}
__device__ __forceinline__ void cp16(uint32_t dst, const void* src) {
    asm volatile("cp.async.cg.shared.global [%0], [%1], 16;" :: "r"(dst), "l"(src));
}
__device__ __forceinline__ void cp_commit() { asm volatile("cp.async.commit_group;"); }
__device__ __forceinline__ void ldsm4(uint32_t& r0, uint32_t& r1, uint32_t& r2, uint32_t& r3,
                                      uint32_t addr) {
    asm volatile("ldmatrix.sync.aligned.m8n8.x4.shared.b16 {%0,%1,%2,%3}, [%4];"
                 : "=r"(r0), "=r"(r1), "=r"(r2), "=r"(r3) : "r"(addr));
}
__device__ __forceinline__ void ldsm4t(uint32_t& r0, uint32_t& r1, uint32_t& r2, uint32_t& r3,
                                       uint32_t addr) {
    asm volatile("ldmatrix.sync.aligned.m8n8.x4.trans.shared.b16 {%0,%1,%2,%3}, [%4];"
                 : "=r"(r0), "=r"(r1), "=r"(r2), "=r"(r3) : "r"(addr));
}
__device__ __forceinline__ void mma_f16(float* d, const uint32_t* a, const uint32_t* b) {
    asm volatile(
        "mma.sync.aligned.m16n8k16.row.col.f32.f16.f16.f32 "
        "{%0,%1,%2,%3}, {%4,%5,%6,%7}, {%8,%9}, {%0,%1,%2,%3};"
        : "+f"(d[0]), "+f"(d[1]), "+f"(d[2]), "+f"(d[3])
        : "r"(a[0]), "r"(a[1]), "r"(a[2]), "r"(a[3]), "r"(b[0]), "r"(b[1]));
}
__device__ __forceinline__ uint32_t swadr(uint32_t tb, int r, int c) {
    return tb + r * 64 + (((c ^ ((r >> 1) & 3))) << 4);
}

// ================= conv_all: x, 4 weights(hi/lo), pos(head-major) ======
__global__ __launch_bounds__(256) void conv_all(
    const float* __restrict__ x, const float* __restrict__ Wq,
    const float* __restrict__ Wk, const float* __restrict__ Wv,
    const float* __restrict__ Wc, const float* __restrict__ pos,
    __half* __restrict__ hf)
{
    const size_t i = (size_t)blockIdx.x * 256 + threadIdx.x;
    if (i < NX) {
        hf[O_XH + i] = __float2half_rn(x[i]);
        return;
    }
    size_t j = i - NX;
    if (j < 4 * NW) {
        const int wi = (int)(j >> 20);
        const size_t off = j & (NW - 1);
        const float* W = (wi == 0) ? Wq : (wi == 1) ? Wk : (wi == 2) ? Wv : Wc;
        __half h, l; splith(W[off], h, l);
        const size_t base = O_WQH + (size_t)wi * 2 * NW;
        hf[base + off] = h;
        hf[base + NW + off] = l;
        return;
    }
    j -= 4 * NW;   // pos head-major
    const int bh = (int)(j >> 16);
    const int s  = (int)((j >> 6) & 1023);
    const int dd = (int)(j & 63);
    const int b = bh >> 4, hh_ = bh & 15;
    hf[O_RHH + j] = __float2half_rn(pos[(((size_t)b << 10) + s) * 1024 + (hh_ << 6) + dd]);
}

// ================= 2-pass projection GEMM, 3-stage pipeline ===========
#define STAGE2_SZ 24576
#define GEMM_SMEM (3 * STAGE2_SZ)

__device__ __forceinline__ void stage_load2(
    uint32_t sb, const __half* Ah, const __half* Bh, const __half* Bl,
    int arow0, int brow0, int k0, int tid)
{
#pragma unroll
    for (int it = 0; it < 6; it++) {
        const int q = it * 256 + tid;          // 0..1535
        const int region = q >> 9;             // 0:A 1:Bh 2:Bl
        const int q2 = q & 511;
        const int r = q2 >> 2, c = q2 & 3;
        const int kel = k0 + c * 8;
        const __half* src = (region == 0) ? (Ah + (size_t)(arow0 + r) * DD + kel)
                         : (region == 1) ? (Bh + (size_t)(brow0 + r) * DD + kel)
                                         : (Bl + (size_t)(brow0 + r) * DD + kel);
        cp16(swadr(sb + region * 8192, r, c), src);
    }
}

__device__ __forceinline__ void compute_chunk2(uint32_t sb, int wm, int wn, int lane,
                                               float acc[4][4][4])
{
    const uint32_t Ab = sb, Bhb = sb + 8192, Blb = sb + 16384;
#pragma unroll
    for (int kk = 0; kk < 2; kk++) {
        uint32_t a[4][4], bh[4][2], bl[4][2];
        const int ar = wm * 64 + (lane & 15);
        const int ac = 2 * kk + (lane >> 4);
#pragma unroll
        for (int i = 0; i < 4; i++)
            ldsm4(a[i][0], a[i][1], a[i][2], a[i][3], swadr(Ab, ar + i * 16, ac));
        const int br = wn * 32 + (lane & 7) + ((lane >> 4) << 3);
        const int bc = 2 * kk + ((lane >> 3) & 1);
#pragma unroll
        for (int p = 0; p < 2; p++) {
            uint32_t t0, t1, t2, t3;
            ldsm4(t0, t1, t2, t3, swadr(Bhb, br + p * 16, bc));
            bh[2*p][0] = t0; bh[2*p][1] = t1; bh[2*p+1][0] = t2; bh[2*p+1][1] = t3;
            ldsm4(t0, t1, t2, t3, swadr(Blb, br + p * 16, bc));
            bl[2*p][0] = t0; bl[2*p][1] = t1; bl[2*p+1][0] = t2; bl[2*p+1][1] = t3;
        }
#pragma unroll
        for (int i = 0; i < 4; i++)
#pragma unroll
            for (int j = 0; j < 4; j++) {
                mma_f16(acc[i][j], a[i], bh[j]);
                mma_f16(acc[i][j], a[i], bl[j]);
            }
    }
}

// mode 0: fp32 [m][n]; 1: (c+u)->o1h,(c+v)->o2h; 2: c->o1h   (head-major fp16)
__global__ __launch_bounds__(256, 1) void mm_gemm(
    const __half* __restrict__ Ah, const __half* __restrict__ Bh,
    const __half* __restrict__ Bl, const float* __restrict__ bias,
    const float* __restrict__ uvec, const float* __restrict__ vvec,
    int mode, float* __restrict__ out_f,
    __half* __restrict__ o1h, __half* __restrict__ o2h)
{
    extern __shared__ __align__(16) char smem[];
    const uint32_t sb0 = smem_u32(smem);
    const int tid = threadIdx.x, lane = tid & 31, w = tid >> 5;
    const int wm = w >> 2, wn = w & 3;
    const int m0 = blockIdx.x * 128, n0 = blockIdx.y * 128;

    float acc[4][4][4];
#pragma unroll
    for (int i = 0; i < 4; i++)
#pragma unroll
        for (int j = 0; j < 4; j++)
#pragma unroll
            for (int q = 0; q < 4; q++) acc[i][j][q] = 0.f;

    // 3-stage prologue
    stage_load2(sb0,              Ah, Bh, Bl, m0, n0, 0,  tid); cp_commit();
    stage_load2(sb0 + STAGE2_SZ,  Ah, Bh, Bl, m0, n0, 32, tid); cp_commit();

    int buf = 0;
    for (int c = 0; c < 32; c++) {
        if (c + 2 < 32) {
            const int nb = (buf + 2 >= 3) ? buf - 1 : buf + 2;
            stage_load2(sb0 + nb * STAGE2_SZ, Ah, Bh, Bl, m0, n0, (c + 2) * 32, tid);
            cp_commit();
            asm volatile("cp.async.wait_group 2;");
        } else if (c + 1 < 32) {
            asm volatile("cp.async.wait_group 1;");
        } else {
            asm volatile("cp.async.wait_group 0;");
        }
        __syncthreads();
        compute_chunk2(sb0 + buf * STAGE2_SZ, wm, wn, lane, acc);
        __syncthreads();
        buf = (buf + 1 == 3) ? 0 : buf + 1;
    }

    const int g = lane >> 2, t2 = (lane & 3) * 2;
#pragma unroll
    for (int i = 0; i < 4; i++)
#pragma unroll
        for (int j = 0; j < 4; j++)
#pragma unroll
            for (int half = 0; half < 2; half++) {
                const int grow = m0 + wm * 64 + i * 16 + g + half * 8;
                const int gcol = n0 + wn * 32 + j * 8 + t2;
                float v0 = acc[i][j][half * 2 + 0] + bias[gcol];
                float v1 = acc[i][j][half * 2 + 1] + bias[gcol + 1];
                if (mode == 0) {
                    *(float2*)&out_f[(size_t)grow * DD + gcol] = make_float2(v0, v1);
                } else {
                    const int b = grow >> 10, s = grow & 1023;
                    const int h = gcol >> 6, dd = gcol & 63;
                    const size_t base = (((size_t)(b * HHN + h) << 10) + s) * DHD + dd;
                    if (mode == 2) {
                        *(__half2*)&o1h[base] = __floats2half2_rn(v0, v1);
                    } else {
                        *(__half2*)&o1h[base] = __floats2half2_rn(v0 + uvec[dd], v1 + uvec[dd + 1]);
                        *(__half2*)&o2h[base] = __floats2half2_rn(v0 + vvec[dd], v1 + vvec[dd + 1]);
                    }
                }
            }
}

// ================= t = (q+v)@r^T single-pass fp16 ======================
#define TSTAGE_SZ 16384
#define T_SMEM (2 * TSTAGE_SZ)

__global__ __launch_bounds__(256, 1) void mm_t(
    const __half* __restrict__ qvh, const __half* __restrict__ rhh,
    __half* __restrict__ tout)
{
    extern __shared__ __align__(16) char smem[];
    const uint32_t sb0 = smem_u32(smem);
    const int tid = threadIdx.x, lane = tid & 31, w = tid >> 5;
    const int wm = w >> 2, wn = w & 3;
    const int bh = blockIdx.z;
    const int m0 = blockIdx.x * 128;
    const int j0 = blockIdx.y * 128;

    const __half* A = qvh + (size_t)bh * SSQ * DHD;
    const __half* B = rhh + (size_t)bh * SSQ * DHD;

    float acc[4][4][4];
#pragma unroll
    for (int i = 0; i < 4; i++)
#pragma unroll
        for (int j = 0; j < 4; j++)
#pragma unroll
            for (int q = 0; q < 4; q++) acc[i][j][q] = 0.f;

#pragma unroll
    for (int c = 0; c < 2; c++) {
        const uint32_t sb = sb0 + c * TSTAGE_SZ;
#pragma unroll
        for (int it = 0; it < 4; it++) {
            const int q = it * 256 + tid;      // 0..1023
            const int region = q >> 9;
            const int q2 = q & 511;
            const int r = q2 >> 2, cc = q2 & 3;
            const int kel = c * 32 + cc * 8;
            const __half* src = region ? (B + (size_t)(m0 + r) * DHD + kel)
                                       : (A + (size_t)(j0 + r) * DHD + kel);
            cp16(swadr(sb + region * 8192, r, cc), src);
        }
        cp_commit();
    }
    asm volatile("cp.async.wait_group 0;");
    __syncthreads();

#pragma unroll
    for (int c = 0; c < 2; c++) {
        const uint32_t Ab = sb0 + c * TSTAGE_SZ, Bb = Ab + 8192;
#pragma unroll
        for (int kk = 0; kk < 2; kk++) {
            uint32_t a[4][4], bfr[4][2];
            const int ar = wm * 64 + (lane & 15);
            const int ac = 2 * kk + (lane >> 4);
#pragma unroll
            for (int i = 0; i < 4; i++)
                ldsm4(a[i][0], a[i][1], a[i][2], a[i][3], swadr(Ab, ar + i * 16, ac));
            const int br = wn * 32 + (lane & 7) + ((lane >> 4) << 3);
            const int bc = 2 * kk + ((lane >> 3) & 1);
#pragma unroll
            for (int p = 0; p < 2; p++) {
                uint32_t t0, t1, t2, t3;
                ldsm4(t0, t1, t2, t3, swadr(Bb, br + p * 16, bc));
                bfr[2*p][0] = t0; bfr[2*p][1] = t1; bfr[2*p+1][0] = t2; bfr[2*p+1][1] = t3;
            }
#pragma unroll
            for (int i = 0; i < 4; i++)
#pragma unroll
                for (int j = 0; j < 4; j++)
                    mma_f16(acc[i][j], a[i], bfr[j]);
        }
    }

    __half* out = tout + (size_t)bh * SSQ * SSQ;
    const int g = lane >> 2, t2 = (lane & 3) * 2;
#pragma unroll
    for (int i = 0; i < 4; i++)
#pragma unroll
        for (int j = 0; j < 4; j++)
#pragma unroll
            for (int half = 0; half < 2; half++) {
                const int grow = j0 + wm * 64 + i * 16 + g + half * 8;
                const int gcol = m0 + wn * 32 + j * 8 + t2;
                *(__half2*)&out[(size_t)grow * SSQ + gcol] =
                    __floats2half2_rn(acc[i][j][half * 2], acc[i][j][half * 2 + 1]);
            }
}

// ================= fused QK^T + rel-shift softmax + PV (3-stage) =======
// per stage: K tile 16K + W tile 16K at sb + s*32768 (K) / +16384 (W)
#define FA_STAGE 32768
#define FA_SMEM (3 * FA_STAGE)

__device__ __forceinline__ void fa_load_k(uint32_t kb, const __half* src0,
                                          int row0, int tid) {
#pragma unroll
    for (int i = 0; i < 4; i++) {
        const int q = i * 256 + tid;           // 0..1023
        const int s = q >> 9;
        const int q2 = q & 511;
        const int r = q2 >> 2, c = q2 & 3;
        cp16(swadr(kb + s * 8192, r, c), src0 + (size_t)(row0 + r) * DHD + s * 32 + c * 8);
    }
}
__device__ __forceinline__ void fa_load_w(uint32_t wb, const __half* src0,
                                          int row0, int tid) {
#pragma unroll
    for (int i = 0; i < 4; i++) {
        const int q = i * 256 + tid;
        const int r = q >> 3, c = q & 7;
        cp16(wb + r * 128 + ((c ^ (r & 7)) << 4), src0 + (size_t)(row0 + r) * DHD + c * 8);
    }
}

__global__ __launch_bounds__(256, 2) void fused_attn(
    const __half* __restrict__ quh, const __half* __restrict__ khh,
    const __half* __restrict__ vwh, const __half* __restrict__ t16,
    __half* __restrict__ obh)
{
    extern __shared__ __align__(16) char smem[];
    const uint32_t sb = smem_u32(smem);
    const int tid = threadIdx.x, lane = tid & 31, w = tid >> 5;
    const int bh = blockIdx.y;
    const int jblk = blockIdx.x * 128;
    const int jw = jblk + w * 16;
    const int g = lane >> 2, t2 = (lane & 3) * 2;

    const size_t hoff = (size_t)bh * SSQ * DHD;
    const __half* kh = khh + hoff;
    const __half* wh = vwh + hoff;

    // stage QU into stage-0 K area, pull q-frags to registers
    fa_load_k(sb, quh + hoff, jblk, tid);
    cp_commit();
    asm volatile("cp.async.wait_group 0;");
    __syncthreads();
    uint32_t qh[4][4];
    {
        const int ar = w * 16 + (lane & 15);
#pragma unroll
        for (int kk4 = 0; kk4 < 4; kk4++) {
            const int s = kk4 >> 1;
            const int cc = 2 * (kk4 & 1) + (lane >> 4);
            ldsm4(qh[kk4][0], qh[kk4][1], qh[kk4][2], qh[kk4][3],
                  swadr(sb + s * 8192, ar, cc));
        }
    }
    __syncthreads();

    const __half* tr0 = t16 + ((size_t)bh * SSQ + jw + g) * SSQ;
    const __half* tr1 = tr0 + (size_t)8 * SSQ;
    const int j0r = jw + g;

    float acc[8][4];
#pragma unroll
    for (int n = 0; n < 8; n++)
#pragma unroll
        for (int q = 0; q < 4; q++) acc[n][q] = 0.f;
    float zlo = 0.f, zhi = 0.f;

    // 3-stage prologue: tiles 0 and 1
    fa_load_k(sb,            kh, 0,   tid);
    fa_load_w(sb + 16384,    wh, 0,   tid);
    cp_commit();
    fa_load_k(sb + FA_STAGE,         kh, 128, tid);
    fa_load_w(sb + FA_STAGE + 16384, wh, 128, tid);
    cp_commit();

    int buf = 0;
    for (int mt = 0; mt < 8; mt++) {
        if (mt + 2 < 8) {
            const int nb = (buf + 2 >= 3) ? buf - 1 : buf + 2;
            fa_load_k(sb + nb * FA_STAGE,         kh, (mt + 2) * 128, tid);
            fa_load_w(sb + nb * FA_STAGE + 16384, wh, (mt + 2) * 128, tid);
            cp_commit();
            asm volatile("cp.async.wait_group 2;");
        } else if (mt + 1 < 8) {
            asm volatile("cp.async.wait_group 1;");
        } else {
            asm volatile("cp.async.wait_group 0;");
        }
        __syncthreads();

        const uint32_t Kb = sb + buf * FA_STAGE;
        const uint32_t Wb = Kb + 16384;
        const int m0 = mt * 128;

#pragma unroll
        for (int half = 0; half < 2; half++) {
            float c[8][4];
#pragma unroll
            for (int n = 0; n < 8; n++)
#pragma unroll
                for (int e = 0; e < 4; e++) c[n][e] = 0.f;

            // QK^T single-pass
#pragma unroll
            for (int kk4 = 0; kk4 < 4; kk4++) {
                const int s = kk4 >> 1;
                const int bc = 2 * (kk4 & 1) + ((lane >> 3) & 1);
                const uint32_t khb = Kb + s * 8192;
#pragma unroll
                for (int p = 0; p < 4; p++) {
                    const int br = half * 64 + p * 16 + (lane & 7) + ((lane >> 4) << 3);
                    uint32_t h0, h1, h2, h3;
                    ldsm4(h0, h1, h2, h3, swadr(khb, br, bc));
                    uint32_t B0[2] = {h0, h1}, B1[2] = {h2, h3};
                    mma_f16(c[2*p],   qh[kk4], B0);
                    mma_f16(c[2*p+1], qh[kk4], B1);
                }
            }

            // bd gather + exp
#pragma unroll
            for (int n = 0; n < 8; n++) {
#pragma unroll
                for (int e = 0; e < 4; e++) {
                    const int m = m0 + half * 64 + n * 8 + t2 + (e & 1);
                    const int j = j0r + ((e >> 1) << 3);
                    const int dlt = m - j;
                    float bd = 0.f;
                    if (dlt != 1) {
                        const int idx = dlt + ((dlt <= 0) ? 1023 : 1022);
                        bd = __half2float((e >> 1) ? tr1[idx] : tr0[idx]);
                    }
                    const float sv = __expf((c[n][e] + bd) * ATT_SCALE);
                    c[n][e] = sv;
                    if (e < 2) zlo += sv; else zhi += sv;
                }
            }

            // PV single-pass
#pragma unroll
            for (int ks = 0; ks < 4; ks++) {
                uint32_t aph[4];
                aph[0] = packh2(c[2*ks][0],   c[2*ks][1]);
                aph[1] = packh2(c[2*ks][2],   c[2*ks][3]);
                aph[2] = packh2(c[2*ks+1][0], c[2*ks+1][1]);
                aph[3] = packh2(c[2*ks+1][2], c[2*ks+1][3]);
                const int krow = half * 64 + ks * 16 + ((lane >> 3) & 1) * 8 + (lane & 7);
#pragma unroll
                for (int g2 = 0; g2 < 4; g2++) {
                    const int nc = g2 * 2 + (lane >> 4);
                    const uint32_t off = krow * 128 + ((nc ^ (krow & 7)) << 4);
                    uint32_t h0, h1, h2, h3;
                    ldsm4t(h0, h1, h2, h3, Wb + off);
                    uint32_t B0[2] = {h0, h1}, B1[2] = {h2, h3};
                    mma_f16(acc[2*g2],   aph, B0);
                    mma_f16(acc[2*g2+1], aph, B1);
                }
            }
        }
        __syncthreads();
        buf = (buf + 1 == 3) ? 0 : buf + 1;
    }

    zlo += __shfl_xor_sync(0xffffffffu, zlo, 1);
    zlo += __shfl_xor_sync(0xffffffffu, zlo, 2);
    zhi += __shfl_xor_sync(0xffffffffu, zhi, 1);
    zhi += __shfl_xor_sync(0xffffffffu, zhi, 2);
    const float inv0 = 1.f / zlo, inv1 = 1.f / zhi;

    const int b = bh >> 4, h = bh & 15;
    const size_t rb0 = ((size_t)(b << 10) + jw + g) << 10;
    const size_t rb1 = ((size_t)(b << 10) + jw + g + 8) << 10;
#pragma unroll
    for (int ng = 0; ng < 8; ng++) {
        const int d = h * 64 + ng * 8 + t2;
        *(__half2*)&obh[rb0 + d] = __floats2half2_rn(acc[ng][0] * inv0, acc[ng][1] * inv0);
        *(__half2*)&obh[rb1 + d] = __floats2half2_rn(acc[ng][2] * inv1, acc[ng][3] * inv1);
    }
}

// =====================================================================
extern "C" void kernel_launch(void* const* d_in, const int* in_sizes, int n_in,
                              void* d_out, int out_size)
{
    const float* x   = (const float*)d_in[0];
    const float* u   = (const float*)d_in[1];
    const float* v   = (const float*)d_in[2];
    const float* pos = (const float*)d_in[3];
    const float* Wq  = (const float*)d_in[4];
    const float* bq  = (const float*)d_in[5];
    const float* Wk  = (const float*)d_in[6];
    const float* bk  = (const float*)d_in[7];
    const float* Wv  = (const float*)d_in[8];
    const float* bv  = (const float*)d_in[9];
    const float* Wc  = (const float*)d_in[10];
    const float* bc  = (const float*)d_in[11];
    float* out = (float*)d_out;

    __half *t16, *hf;
    cudaGetSymbolAddress((void**)&t16, g_t16);
    cudaGetSymbolAddress((void**)&hf,  g_hf);

    cudaFuncSetAttribute(mm_gemm, cudaFuncAttributeMaxDynamicSharedMemorySize, GEMM_SMEM);
    cudaFuncSetAttribute(mm_t,    cudaFuncAttributeMaxDynamicSharedMemorySize, T_SMEM);
    cudaFuncSetAttribute(fused_attn, cudaFuncAttributeMaxDynamicSharedMemorySize, FA_SMEM);

    // 1: conversions (x hi, weights hi/lo, pos head-major hi)
    const size_t total = NX + 4 * NW + NH;
    conv_all<<<(int)((total + 255) / 256), 256>>>(x, Wq, Wk, Wv, Wc, pos, hf);

    dim3 gp(32, 8);
    // 2-4: projections
    mm_gemm<<<gp, 256, GEMM_SMEM>>>(hf + O_XH, hf + O_WQH, hf + O_WQL,
        bq, u, v, 1, nullptr, hf + O_QUH, hf + O_QVH);
    mm_gemm<<<gp, 256, GEMM_SMEM>>>(hf + O_XH, hf + O_WKH, hf + O_WKL,
        bk, u, v, 2, nullptr, hf + O_KHH, nullptr);
    mm_gemm<<<gp, 256, GEMM_SMEM>>>(hf + O_XH, hf + O_WVH, hf + O_WVL,
        bv, u, v, 2, nullptr, hf + O_VWH, nullptr);

    // 5: t matrix
    mm_t<<<dim3(8, 8, 64), 256, T_SMEM>>>(hf + O_QVH, hf + O_RHH, t16);

    // 6: fused attention  (this is the ncu-profiled launch)
    fused_attn<<<dim3(8, 64), 256, FA_SMEM>>>(
        hf + O_QUH, hf + O_KHH, hf + O_VWH, t16, hf + O_OBH);

    // 7: output projection
    mm_gemm<<<gp, 256, GEMM_SMEM>>>(hf + O_OBH, hf + O_WCH, hf + O_WCL,
        bc, u, v, 0, out, nullptr, nullptr);
}